// round 12
// baseline (speedup 1.0000x reference)
#include <cuda_runtime.h>
#include <cuda_bf16.h>
#include <cstdint>
#include <math.h>

#define HIDDEN 1024
#define HEADS  16
#define HD     64
#define SEQ    2048
#define BATCH  4
#define M_TOT  (BATCH*SEQ)   // 8192

// ---------------- scratch (device globals: allocation-free) ----------------
__device__ float g_q[(size_t)M_TOT * HIDDEN];
__device__ float g_k[(size_t)M_TOT * HIDDEN];
__device__ float g_v[(size_t)M_TOT * HIDDEN];
__device__ float g_attn[(size_t)M_TOT * HIDDEN];
__device__ int   g_bflag[(SEQ/128) * (SEQ/64)];

__device__ __nv_bfloat16 g_qhi[(size_t)M_TOT * HIDDEN];
__device__ __nv_bfloat16 g_qlo[(size_t)M_TOT * HIDDEN];
__device__ __nv_bfloat16 g_ahi[(size_t)M_TOT * HIDDEN];
__device__ __nv_bfloat16 g_alo[(size_t)M_TOT * HIDDEN];
__device__ __nv_bfloat16 g_whi[4][(size_t)HIDDEN * HIDDEN];
__device__ __nv_bfloat16 g_wlo[4][(size_t)HIDDEN * HIDDEN];

// ---------------------------------------------------------------------------
// helpers
// ---------------------------------------------------------------------------
__device__ __forceinline__ unsigned f2tf(float x) {
    unsigned r;
    asm("cvt.rna.tf32.f32 %0, %1;" : "=r"(r) : "f"(x));
    return r;
}

__device__ __forceinline__ void mma_tf32(float* c,
    unsigned a0, unsigned a1, unsigned a2, unsigned a3,
    unsigned b0, unsigned b1)
{
    asm volatile(
        "mma.sync.aligned.m16n8k8.row.col.f32.tf32.tf32.f32 "
        "{%0,%1,%2,%3}, {%4,%5,%6,%7}, {%8,%9}, {%0,%1,%2,%3};\n"
        : "+f"(c[0]), "+f"(c[1]), "+f"(c[2]), "+f"(c[3])
        : "r"(a0), "r"(a1), "r"(a2), "r"(a3), "r"(b0), "r"(b1));
}

__device__ __forceinline__ void mma_bf16(float* c,
    unsigned a0, unsigned a1, unsigned a2, unsigned a3,
    unsigned b0, unsigned b1)
{
    asm volatile(
        "mma.sync.aligned.m16n8k16.row.col.f32.bf16.bf16.f32 "
        "{%0,%1,%2,%3}, {%4,%5,%6,%7}, {%8,%9}, {%0,%1,%2,%3};\n"
        : "+f"(c[0]), "+f"(c[1]), "+f"(c[2]), "+f"(c[3])
        : "r"(a0), "r"(a1), "r"(a2), "r"(a3), "r"(b0), "r"(b1));
}

__device__ __forceinline__ void ldsm_x4(unsigned* r, uint32_t addr) {
    asm volatile(
        "ldmatrix.sync.aligned.m8n8.x4.shared.b16 {%0,%1,%2,%3}, [%4];"
        : "=r"(r[0]), "=r"(r[1]), "=r"(r[2]), "=r"(r[3])
        : "r"(addr));
}

__device__ __forceinline__ uint32_t smem_u32(const void* p) {
    uint32_t a;
    asm("{ .reg .u64 t; cvta.to.shared.u64 t, %1; cvt.u32.u64 %0, t; }"
        : "=r"(a) : "l"(p));
    return a;
}

__device__ __forceinline__ void cp16(uint32_t dst, const void* src) {
    asm volatile("cp.async.cg.shared.global [%0], [%1], 16;"
                 :: "r"(dst), "l"(src) : "memory");
}
#define CP_COMMIT() asm volatile("cp.async.commit_group;" ::: "memory")
#define CP_WAIT0()  asm volatile("cp.async.wait_group 0;" ::: "memory")

// ---------------------------------------------------------------------------
// hi/lo bf16 decomposition: hi = bf16(x), lo = bf16(x - hi)
// ---------------------------------------------------------------------------
__global__ __launch_bounds__(256) void decomp_k(
    const float* __restrict__ in, __nv_bfloat16* __restrict__ hi,
    __nv_bfloat16* __restrict__ lo, int n4)
{
    int i = blockIdx.x * 256 + threadIdx.x;
    if (i >= n4) return;
    float4 v = ((const float4*)in)[i];
    __nv_bfloat16 h0 = __float2bfloat16_rn(v.x);
    __nv_bfloat16 h1 = __float2bfloat16_rn(v.y);
    __nv_bfloat16 h2 = __float2bfloat16_rn(v.z);
    __nv_bfloat16 h3 = __float2bfloat16_rn(v.w);
    __nv_bfloat162* hp = (__nv_bfloat162*)hi;
    hp[2*i]   = __nv_bfloat162(h0, h1);
    hp[2*i+1] = __nv_bfloat162(h2, h3);
    __nv_bfloat16 l0 = __float2bfloat16_rn(v.x - __bfloat162float(h0));
    __nv_bfloat16 l1 = __float2bfloat16_rn(v.y - __bfloat162float(h1));
    __nv_bfloat16 l2 = __float2bfloat16_rn(v.z - __bfloat162float(h2));
    __nv_bfloat16 l3 = __float2bfloat16_rn(v.w - __bfloat162float(h3));
    __nv_bfloat162* lp = (__nv_bfloat162*)lo;
    lp[2*i]   = __nv_bfloat162(l0, l1);
    lp[2*i+1] = __nv_bfloat162(l2, l3);
}

// ---------------------------------------------------------------------------
// bias tile flags
// ---------------------------------------------------------------------------
__global__ __launch_bounds__(256) void bias_flags(const float* __restrict__ bias,
                                                  int* __restrict__ flags)
{
    const int qt = blockIdx.x >> 5;
    const int kt = blockIdx.x & 31;
    const int tid = threadIdx.x;
    bool nz = false;
    #pragma unroll
    for (int r = 0; r < 8; r++) {
        int f   = tid + r * 256;
        int row = f >> 4;
        int cq  = (f & 15) << 2;
        float4 v = *(const float4*)(bias + (size_t)(qt * 128 + row) * SEQ + kt * 64 + cq);
        nz |= (v.x != 0.f) | (v.y != 0.f) | (v.z != 0.f) | (v.w != 0.f);
    }
    int any = __syncthreads_or((int)nz);
    if (tid == 0) flags[blockIdx.x] = any;
}

// ---------------------------------------------------------------------------
// bf16x3 GEMM: C = scale*(A@W^T + bias), A/W pre-split into bf16 hi/lo.
// CTA 128x128x32, 8 warps (2m x 4n), warp tile 64x32.
// m16n8k16 bf16 MMA; acc += Ahi*Whi + Ahi*Wlo + Alo*Whi.
// cp.async 2-stage pipeline, 1 sync/iter. ldmatrix b16 fragments.
// ---------------------------------------------------------------------------
#define GK 1024
#define BSTRB 80              // bytes per smem row (40 bf16): conflict-free + 16B-aligned
#define TEN_B (128*BSTRB)     // 10240 B per tensor per stage
#define STG_B (4*TEN_B)       // Ahi,Alo,Whi,Wlo
#define GEMM_SMEM (2*STG_B)   // 81920 B

__global__ __launch_bounds__(256, 2) void gemm_bf16x3(
    const __nv_bfloat16* __restrict__ Ahi, const __nv_bfloat16* __restrict__ Alo,
    const __nv_bfloat16* __restrict__ Whi, const __nv_bfloat16* __restrict__ Wlo,
    const float* __restrict__ bias, float* __restrict__ C, float scale)
{
    extern __shared__ char gsm[];
    const uint32_t sb = smem_u32(gsm);

    const int tid  = threadIdx.x;
    const int lane = tid & 31;
    const int warp = tid >> 5;
    const int g    = lane >> 2;
    const int tig  = lane & 3;
    const int wm   = (warp >> 2) * 64;
    const int wn   = (warp & 3) * 32;
    const int m0   = blockIdx.y * 128;
    const int n0   = blockIdx.x * 128;

    const __nv_bfloat16* srcs[4] = {
        Ahi + (size_t)m0 * GK, Alo + (size_t)m0 * GK,
        Whi + (size_t)n0 * GK, Wlo + (size_t)n0 * GK };

    // fragment addresses (ldmatrix b16)
    const uint32_t aHi = sb + (uint32_t)((wm + (lane & 15)) * BSTRB + (lane >> 4) * 16);
    const uint32_t aLo = aHi + TEN_B;
    const int wrow = wn + ((lane >> 4) << 3) + (lane & 7);
    const uint32_t wHi = sb + 2 * TEN_B + (uint32_t)(wrow * BSTRB + ((lane >> 3) & 1) * 16);
    const uint32_t wLo = wHi + TEN_B;

    float acc[4][4][4];
    #pragma unroll
    for (int i = 0; i < 4; i++)
        #pragma unroll
        for (int j = 0; j < 4; j++)
            #pragma unroll
            for (int e = 0; e < 4; e++) acc[i][j][e] = 0.f;

    // copy helper: 8 chunks of 16B per thread per stage
    auto issue = [&](int stage, int k0) {
        #pragma unroll
        for (int t = 0; t < 8; t++) {
            int t2  = t >> 1;
            int cid = tid + (t & 1) * 256;   // 0..511
            int row = cid >> 2;
            int c16 = cid & 3;
            const void* src = srcs[t2] + (size_t)row * GK + k0 + c16 * 8;
            uint32_t dst = sb + (uint32_t)(stage * STG_B + t2 * TEN_B + row * BSTRB + c16 * 16);
            cp16(dst, src);
        }
        CP_COMMIT();
    };

    issue(0, 0);

    for (int c = 0; c < GK / 32; c++) {
        const int cur = c & 1;
        CP_WAIT0();
        __syncthreads();
        if (c + 1 < GK / 32) issue(cur ^ 1, (c + 1) * 32);

        const uint32_t sOff = (uint32_t)(cur * STG_B);
        #pragma unroll
        for (int kt = 0; kt < 2; kt++) {
            const uint32_t ktB = (uint32_t)(kt * 32);
            unsigned ahi[4][4], alo[4][4], whi[2][4], wlo[2][4];
            #pragma unroll
            for (int mt = 0; mt < 4; mt++) {
                ldsm_x4(ahi[mt], aHi + sOff + (uint32_t)(mt * 16 * BSTRB) + ktB);
                ldsm_x4(alo[mt], aLo + sOff + (uint32_t)(mt * 16 * BSTRB) + ktB);
            }
            #pragma unroll
            for (int p = 0; p < 2; p++) {
                ldsm_x4(whi[p], wHi + sOff + (uint32_t)(p * 16 * BSTRB) + ktB);
                ldsm_x4(wlo[p], wLo + sOff + (uint32_t)(p * 16 * BSTRB) + ktB);
            }
            #pragma unroll
            for (int mt = 0; mt < 4; mt++) {
                #pragma unroll
                for (int p = 0; p < 2; p++) {
                    // n-block even (regs 0,1) and odd (regs 2,3)
                    mma_bf16(acc[mt][2*p],   ahi[mt][0], ahi[mt][1], ahi[mt][2], ahi[mt][3],
                             whi[p][0], whi[p][1]);
                    mma_bf16(acc[mt][2*p],   ahi[mt][0], ahi[mt][1], ahi[mt][2], ahi[mt][3],
                             wlo[p][0], wlo[p][1]);
                    mma_bf16(acc[mt][2*p],   alo[mt][0], alo[mt][1], alo[mt][2], alo[mt][3],
                             whi[p][0], whi[p][1]);
                    mma_bf16(acc[mt][2*p+1], ahi[mt][0], ahi[mt][1], ahi[mt][2], ahi[mt][3],
                             whi[p][2], whi[p][3]);
                    mma_bf16(acc[mt][2*p+1], ahi[mt][0], ahi[mt][1], ahi[mt][2], ahi[mt][3],
                             wlo[p][2], wlo[p][3]);
                    mma_bf16(acc[mt][2*p+1], alo[mt][0], alo[mt][1], alo[mt][2], alo[mt][3],
                             whi[p][2], whi[p][3]);
                }
            }
        }
        __syncthreads();
    }

    #pragma unroll
    for (int mt = 0; mt < 4; mt++) {
        #pragma unroll
        for (int nt = 0; nt < 4; nt++) {
            int ncol = n0 + wn + nt * 8 + 2 * tig;
            float2 bv = *(const float2*)(bias + ncol);
            int r0 = m0 + wm + mt * 16 + g;
            *(float2*)(C + (size_t)r0 * HIDDEN + ncol) =
                make_float2(scale * (acc[mt][nt][0] + bv.x), scale * (acc[mt][nt][1] + bv.y));
            *(float2*)(C + (size_t)(r0 + 8) * HIDDEN + ncol) =
                make_float2(scale * (acc[mt][nt][2] + bv.x), scale * (acc[mt][nt][3] + bv.y));
        }
    }
}

// ---------------------------------------------------------------------------
// Flash attention (unchanged from R6): tf32 mma + ldmatrix, single-buffered
// K/V, 2 CTAs/SM, register prefetch, two syncs per 64-key chunk.
// ---------------------------------------------------------------------------
#define QSS 68
#define VSS 72
#define ATTN_SMEM ((128*QSS + 128*QSS + 64*QSS + 64*VSS) * 4)   // 105472 B

__global__ __launch_bounds__(256, 2) void attn_tf32(
    const float* __restrict__ Q, const float* __restrict__ K,
    const float* __restrict__ V, const float* __restrict__ bias,
    const int* __restrict__ flags, float* __restrict__ O)
{
    extern __shared__ unsigned sm[];
    unsigned* Qs = sm;
    unsigned* Ps = Qs + 128 * QSS;
    unsigned* Ks = Ps + 128 * QSS;
    unsigned* Vs = Ks + 64 * QSS;
    const uint32_t sbQ = smem_u32(Qs);
    const uint32_t sbP = smem_u32(Ps);
    const uint32_t sbK = smem_u32(Ks);

    const int tid  = threadIdx.x;
    const int lane = tid & 31;
    const int warp = tid >> 5;
    const int g    = lane >> 2;
    const int tig  = lane & 3;
    const int q0   = blockIdx.x * 128;
    const int h    = blockIdx.y;
    const int b    = blockIdx.z;
    const size_t base = (size_t)b * SEQ * HIDDEN + (size_t)h * HD;
    const int qb   = warp * 16;

    const int srow = tid >> 4;
    const int sdq  = (tid & 15) << 2;

    const int rA = (lane & 7) + ((lane >> 3) & 1) * 8;
    const int cA = (lane >> 4) * 4;
    const uint32_t qAddr0 = sbQ + (uint32_t)(((qb + rA) * QSS + cA) * 4);
    const uint32_t pAddr0 = sbP + (uint32_t)(((qb + rA) * QSS + cA) * 4);
    const int rB = (lane & 7) + (lane >> 4) * 8;
    const int cB = ((lane >> 3) & 1) * 4;
    const uint32_t kAddr0 = sbK + (uint32_t)((rB * QSS + cB) * 4);

    #pragma unroll
    for (int r = 0; r < 8; r++) {
        int row = srow + 16 * r;
        float4 v = *(const float4*)(Q + base + (size_t)(q0 + row) * HIDDEN + sdq);
        *(uint4*)&Qs[row * QSS + sdq] =
            make_uint4(f2tf(v.x), f2tf(v.y), f2tf(v.z), f2tf(v.w));
    }

    float4 pk[4], pv4[4];
    #pragma unroll
    for (int r = 0; r < 4; r++) {
        int row = srow + 16 * r;
        pk[r]  = *(const float4*)(K + base + (size_t)row * HIDDEN + sdq);
        pv4[r] = *(const float4*)(V + base + (size_t)row * HIDDEN + sdq);
    }
    #pragma unroll
    for (int r = 0; r < 4; r++) {
        int row = srow + 16 * r;
        *(uint4*)&Ks[row * QSS + sdq] =
            make_uint4(f2tf(pk[r].x), f2tf(pk[r].y), f2tf(pk[r].z), f2tf(pk[r].w));
        *(uint4*)&Vs[row * VSS + sdq] =
            make_uint4(f2tf(pv4[r].x), f2tf(pv4[r].y), f2tf(pv4[r].z), f2tf(pv4[r].w));
    }
    __syncthreads();

    float o[8][4];
    float mr[2], lr[2];
    mr[0] = mr[1] = -1e30f;
    lr[0] = lr[1] = 0.f;
    #pragma unroll
    for (int nt = 0; nt < 8; nt++)
        #pragma unroll
        for (int e = 0; e < 4; e++) o[nt][e] = 0.f;

    const int qr = qb + g;

    for (int c = 0; c < SEQ / 64; c++) {
        const bool more = (c + 1 < SEQ / 64);

        if (more) {
            const int k1 = (c + 1) * 64;
            #pragma unroll
            for (int r = 0; r < 4; r++) {
                int row = srow + 16 * r;
                pk[r]  = *(const float4*)(K + base + (size_t)(k1 + row) * HIDDEN + sdq);
                pv4[r] = *(const float4*)(V + base + (size_t)(k1 + row) * HIDDEN + sdq);
            }
        }

        float s[8][4];
        #pragma unroll
        for (int nt = 0; nt < 8; nt++)
            #pragma unroll
            for (int e = 0; e < 4; e++) s[nt][e] = 0.f;

        #pragma unroll
        for (int kt = 0; kt < 8; kt++) {
            const uint32_t kbB = (uint32_t)(kt * 8 * 4);
            unsigned qf[4], kf[4][4];
            ldsm_x4(qf, qAddr0 + kbB);
            #pragma unroll
            for (int p = 0; p < 4; p++)
                ldsm_x4(kf[p], kAddr0 + (uint32_t)(p * 16 * QSS * 4) + kbB);
            #pragma unroll
            for (int p = 0; p < 4; p++) {
                mma_tf32(s[2*p],   qf[0], qf[1], qf[2], qf[3], kf[p][0], kf[p][1]);
                mma_tf32(s[2*p+1], qf[0], qf[1], qf[2], qf[3], kf[p][2], kf[p][3]);
            }
        }

        if (flags[blockIdx.x * (SEQ / 64) + c]) {
            const int k0 = c * 64;
            int r0 = q0 + qr;
            #pragma unroll
            for (int nt = 0; nt < 8; nt++) {
                int col = k0 + nt * 8 + 2 * tig;
                float2 b0 = *(const float2*)(bias + (size_t)r0 * SEQ + col);
                s[nt][0] += b0.x; s[nt][1] += b0.y;
                float2 b1 = *(const float2*)(bias + (size_t)(r0 + 8) * SEQ + col);
                s[nt][2] += b1.x; s[nt][3] += b1.y;
            }
        }

        #pragma unroll
        for (int h2 = 0; h2 < 2; h2++) {
            float mx = -1e30f;
            #pragma unroll
            for (int nt = 0; nt < 8; nt++)
                mx = fmaxf(mx, fmaxf(s[nt][2 * h2], s[nt][2 * h2 + 1]));
            mx = fmaxf(mx, __shfl_xor_sync(0xffffffffu, mx, 1));
            mx = fmaxf(mx, __shfl_xor_sync(0xffffffffu, mx, 2));
            float mn = fmaxf(mr[h2], mx);
            float al = __expf(mr[h2] - mn);
            mr[h2] = mn;
            float sum = 0.f;
            #pragma unroll
            for (int nt = 0; nt < 8; nt++) {
                float p0 = __expf(s[nt][2 * h2]     - mn);
                float p1 = __expf(s[nt][2 * h2 + 1] - mn);
                s[nt][2 * h2] = p0;  s[nt][2 * h2 + 1] = p1;
                sum += p0 + p1;
            }
            sum += __shfl_xor_sync(0xffffffffu, sum, 1);
            sum += __shfl_xor_sync(0xffffffffu, sum, 2);
            lr[h2] = lr[h2] * al + sum;
            #pragma unroll
            for (int nt = 0; nt < 8; nt++) {
                o[nt][2 * h2]     *= al;
                o[nt][2 * h2 + 1] *= al;
            }
        }

        #pragma unroll
        for (int nt = 0; nt < 8; nt++) {
            int col = nt * 8 + 2 * tig;
            *(uint2*)&Ps[qr * QSS + col] =
                make_uint2(f2tf(s[nt][0]), f2tf(s[nt][1]));
            *(uint2*)&Ps[(qr + 8) * QSS + col] =
                make_uint2(f2tf(s[nt][2]), f2tf(s[nt][3]));
        }
        __syncwarp();

        #pragma unroll
        for (int kt = 0; kt < 8; kt++) {
            const int kb = kt * 8;
            unsigned pf[4];
            ldsm_x4(pf, pAddr0 + (uint32_t)(kb * 4));
            #pragma unroll
            for (int nt = 0; nt < 8; nt++) {
                const unsigned* vp = Vs + (kb + tig) * VSS + nt * 8 + g;
                mma_tf32(o[nt], pf[0], pf[1], pf[2], pf[3], vp[0], vp[4 * VSS]);
            }
        }

        if (more) {
            __syncthreads();
            #pragma unroll
            for (int r = 0; r < 4; r++) {
                int row = srow + 16 * r;
                *(uint4*)&Ks[row * QSS + sdq] =
                    make_uint4(f2tf(pk[r].x), f2tf(pk[r].y), f2tf(pk[r].z), f2tf(pk[r].w));
                *(uint4*)&Vs[row * VSS + sdq] =
                    make_uint4(f2tf(pv4[r].x), f2tf(pv4[r].y), f2tf(pv4[r].z), f2tf(pv4[r].w));
            }
            __syncthreads();
        }
    }

    float inv0 = 1.f / lr[0];
    float inv1 = 1.f / lr[1];
    int r0 = q0 + qr;
    #pragma unroll
    for (int nt = 0; nt < 8; nt++) {
        int col = h * HD + nt * 8 + 2 * tig;
        *(float2*)(O + (size_t)b * SEQ * HIDDEN + (size_t)r0 * HIDDEN + col) =
            make_float2(o[nt][0] * inv0, o[nt][1] * inv0);
        *(float2*)(O + (size_t)b * SEQ * HIDDEN + (size_t)(r0 + 8) * HIDDEN + col) =
            make_float2(o[nt][2] * inv1, o[nt][3] * inv1);
    }
}

// ---------------------------------------------------------------------------
extern "C" void kernel_launch(void* const* d_in, const int* in_sizes, int n_in,
                              void* d_out, int out_size)
{
    (void)in_sizes; (void)n_in; (void)out_size;
    const float* query = (const float*)d_in[0];
    const float* bias  = (const float*)d_in[1];
    const float* wq    = (const float*)d_in[2];
    const float* bq    = (const float*)d_in[3];
    const float* wk    = (const float*)d_in[4];
    const float* bk    = (const float*)d_in[5];
    const float* wv    = (const float*)d_in[6];
    const float* bv    = (const float*)d_in[7];
    const float* wo    = (const float*)d_in[8];
    const float* bo    = (const float*)d_in[9];
    float* out = (float*)d_out;

    float *qb, *kb, *vb, *ab;
    int* bfl;
    __nv_bfloat16 *qhi, *qlo, *ahi, *alo, *whi, *wlo;
    cudaGetSymbolAddress((void**)&qb, g_q);
    cudaGetSymbolAddress((void**)&kb, g_k);
    cudaGetSymbolAddress((void**)&vb, g_v);
    cudaGetSymbolAddress((void**)&ab, g_attn);
    cudaGetSymbolAddress((void**)&bfl, g_bflag);
    cudaGetSymbolAddress((void**)&qhi, g_qhi);
    cudaGetSymbolAddress((void**)&qlo, g_qlo);
    cudaGetSymbolAddress((void**)&ahi, g_ahi);
    cudaGetSymbolAddress((void**)&alo, g_alo);
    cudaGetSymbolAddress((void**)&whi, g_whi);
    cudaGetSymbolAddress((void**)&wlo, g_wlo);

    const size_t WN = (size_t)HIDDEN * HIDDEN;

    cudaFuncSetAttribute(gemm_bf16x3,
                         cudaFuncAttributeMaxDynamicSharedMemorySize, GEMM_SMEM);
    cudaFuncSetAttribute(attn_tf32,
                         cudaFuncAttributeMaxDynamicSharedMemorySize, ATTN_SMEM);

    bias_flags<<<(SEQ/128) * (SEQ/64), 256>>>(bias, bfl);

    const int actN4 = (int)((size_t)M_TOT * HIDDEN / 4);   // 2M
    const int wN4   = (int)(WN / 4);                       // 256K
    decomp_k<<<(actN4 + 255) / 256, 256>>>(query, qhi, qlo, actN4);
    decomp_k<<<(wN4 + 255) / 256, 256>>>(wq, whi + 0 * WN, wlo + 0 * WN, wN4);
    decomp_k<<<(wN4 + 255) / 256, 256>>>(wk, whi + 1 * WN, wlo + 1 * WN, wN4);
    decomp_k<<<(wN4 + 255) / 256, 256>>>(wv, whi + 2 * WN, wlo + 2 * WN, wN4);
    decomp_k<<<(wN4 + 255) / 256, 256>>>(wo, whi + 3 * WN, wlo + 3 * WN, wN4);

    dim3 ggrid(HIDDEN / 128, M_TOT / 128);   // (8, 64)
    const float qscale = 0.125f;             // 64^-0.5

    gemm_bf16x3<<<ggrid, 256, GEMM_SMEM>>>(qhi, qlo, whi + 0*WN, wlo + 0*WN, bq, qb, qscale);
    gemm_bf16x3<<<ggrid, 256, GEMM_SMEM>>>(qhi, qlo, whi + 1*WN, wlo + 1*WN, bk, kb, 1.0f);
    gemm_bf16x3<<<ggrid, 256, GEMM_SMEM>>>(qhi, qlo, whi + 2*WN, wlo + 2*WN, bv, vb, 1.0f);

    dim3 agrid(SEQ / 128, HEADS, BATCH);     // (16, 16, 4)
    attn_tf32<<<agrid, 256, ATTN_SMEM>>>(qb, kb, vb, bias, bfl, ab);

    decomp_k<<<(actN4 + 255) / 256, 256>>>(ab, ahi, alo, actN4);
    gemm_bf16x3<<<ggrid, 256, GEMM_SMEM>>>(ahi, alo, whi + 3*WN, wlo + 3*WN, bo, out, 1.0f);
}

// round 13
// speedup vs baseline: 1.4713x; 1.4713x over previous
#include <cuda_runtime.h>
#include <cuda_fp16.h>
#include <cstdint>
#include <math.h>

#define HIDDEN 1024
#define HEADS  16
#define HD     64
#define SEQ    2048
#define BATCH  4
#define M_TOT  (BATCH*SEQ)   // 8192

// ---------------- scratch (device globals: allocation-free) ----------------
__device__ float g_q[(size_t)M_TOT * HIDDEN];
__device__ float g_k[(size_t)M_TOT * HIDDEN];
__device__ float g_v[(size_t)M_TOT * HIDDEN];
__device__ float g_attn[(size_t)M_TOT * HIDDEN];
__device__ int   g_bflag[(SEQ/128) * (SEQ/64)];

__device__ __half g_qh[(size_t)M_TOT * HIDDEN];
__device__ __half g_ah[(size_t)M_TOT * HIDDEN];
__device__ __half g_wh[4][(size_t)HIDDEN * HIDDEN];

// ---------------------------------------------------------------------------
// helpers
// ---------------------------------------------------------------------------
__device__ __forceinline__ unsigned f2tf(float x) {
    unsigned r;
    asm("cvt.rna.tf32.f32 %0, %1;" : "=r"(r) : "f"(x));
    return r;
}

__device__ __forceinline__ void mma_tf32(float* c,
    unsigned a0, unsigned a1, unsigned a2, unsigned a3,
    unsigned b0, unsigned b1)
{
    asm volatile(
        "mma.sync.aligned.m16n8k8.row.col.f32.tf32.tf32.f32 "
        "{%0,%1,%2,%3}, {%4,%5,%6,%7}, {%8,%9}, {%0,%1,%2,%3};\n"
        : "+f"(c[0]), "+f"(c[1]), "+f"(c[2]), "+f"(c[3])
        : "r"(a0), "r"(a1), "r"(a2), "r"(a3), "r"(b0), "r"(b1));
}

__device__ __forceinline__ void mma_f16(float* c,
    unsigned a0, unsigned a1, unsigned a2, unsigned a3,
    unsigned b0, unsigned b1)
{
    asm volatile(
        "mma.sync.aligned.m16n8k16.row.col.f32.f16.f16.f32 "
        "{%0,%1,%2,%3}, {%4,%5,%6,%7}, {%8,%9}, {%0,%1,%2,%3};\n"
        : "+f"(c[0]), "+f"(c[1]), "+f"(c[2]), "+f"(c[3])
        : "r"(a0), "r"(a1), "r"(a2), "r"(a3), "r"(b0), "r"(b1));
}

__device__ __forceinline__ void ldsm_x4(unsigned* r, uint32_t addr) {
    asm volatile(
        "ldmatrix.sync.aligned.m8n8.x4.shared.b16 {%0,%1,%2,%3}, [%4];"
        : "=r"(r[0]), "=r"(r[1]), "=r"(r[2]), "=r"(r[3])
        : "r"(addr));
}

__device__ __forceinline__ uint32_t smem_u32(const void* p) {
    uint32_t a;
    asm("{ .reg .u64 t; cvta.to.shared.u64 t, %1; cvt.u32.u64 %0, t; }"
        : "=r"(a) : "l"(p));
    return a;
}

__device__ __forceinline__ void cp16(uint32_t dst, const void* src) {
    asm volatile("cp.async.cg.shared.global [%0], [%1], 16;"
                 :: "r"(dst), "l"(src) : "memory");
}
#define CP_COMMIT() asm volatile("cp.async.commit_group;" ::: "memory")
#define CP_WAIT0()  asm volatile("cp.async.wait_group 0;" ::: "memory")

// ---------------------------------------------------------------------------
// f32 -> f16 conversion
// ---------------------------------------------------------------------------
__global__ __launch_bounds__(256) void conv_h(
    const float* __restrict__ in, __half* __restrict__ out, int n4)
{
    int i = blockIdx.x * 256 + threadIdx.x;
    if (i >= n4) return;
    float4 v = ((const float4*)in)[i];
    __half2* op = (__half2*)out;
    op[2*i]   = __floats2half2_rn(v.x, v.y);
    op[2*i+1] = __floats2half2_rn(v.z, v.w);
}

// ---------------------------------------------------------------------------
// bias tile flags
// ---------------------------------------------------------------------------
__global__ __launch_bounds__(256) void bias_flags(const float* __restrict__ bias,
                                                  int* __restrict__ flags)
{
    const int qt = blockIdx.x >> 5;
    const int kt = blockIdx.x & 31;
    const int tid = threadIdx.x;
    bool nz = false;
    #pragma unroll
    for (int r = 0; r < 8; r++) {
        int f   = tid + r * 256;
        int row = f >> 4;
        int cq  = (f & 15) << 2;
        float4 v = *(const float4*)(bias + (size_t)(qt * 128 + row) * SEQ + kt * 64 + cq);
        nz |= (v.x != 0.f) | (v.y != 0.f) | (v.z != 0.f) | (v.w != 0.f);
    }
    int any = __syncthreads_or((int)nz);
    if (tid == 0) flags[blockIdx.x] = any;
}

// ---------------------------------------------------------------------------
// fp16 GEMM: C = scale*(A@W^T + bias), A/W pre-converted to fp16.
// CTA 128x128x32, 8 warps (2m x 4n), warp tile 64x32, m16n8k16 f16 MMA
// (f32 accum). cp.async 2-stage pipeline, ldmatrix fragments.
// Layout identical to the correctness-proven bf16x3 kernel (lo-terms dropped).
// ---------------------------------------------------------------------------
#define GK 1024
#define BSTRB 80              // bytes per smem row (40 halfs): conflict-free, 16B-aligned
#define TEN_B (128*BSTRB)     // 10240 B per tensor per stage
#define STG_B (2*TEN_B)       // A, W
#define GEMM_SMEM (2*STG_B)   // 40960 B

__global__ __launch_bounds__(256, 2) void gemm_f16(
    const __half* __restrict__ Ah, const __half* __restrict__ Wh,
    const float* __restrict__ bias, float* __restrict__ C, float scale)
{
    extern __shared__ char gsm[];
    const uint32_t sb = smem_u32(gsm);

    const int tid  = threadIdx.x;
    const int lane = tid & 31;
    const int warp = tid >> 5;
    const int g    = lane >> 2;
    const int tig  = lane & 3;
    const int wm   = (warp >> 2) * 64;
    const int wn   = (warp & 3) * 32;
    const int m0   = blockIdx.y * 128;
    const int n0   = blockIdx.x * 128;

    const __half* srcs[2] = { Ah + (size_t)m0 * GK, Wh + (size_t)n0 * GK };

    // fragment addresses (ldmatrix b16) — proven in bf16x3 kernel
    const uint32_t aB = sb + (uint32_t)((wm + (lane & 15)) * BSTRB + (lane >> 4) * 16);
    const int wrow = wn + ((lane >> 4) << 3) + (lane & 7);
    const uint32_t wB = sb + TEN_B + (uint32_t)(wrow * BSTRB + ((lane >> 3) & 1) * 16);

    float acc[4][4][4];
    #pragma unroll
    for (int i = 0; i < 4; i++)
        #pragma unroll
        for (int j = 0; j < 4; j++)
            #pragma unroll
            for (int e = 0; e < 4; e++) acc[i][j][e] = 0.f;

    // copy helper: 4 chunks of 16B per thread per stage
    auto issue = [&](int stage, int k0) {
        #pragma unroll
        for (int t = 0; t < 4; t++) {
            int t2  = t >> 1;                // 0=A, 1=W
            int cid = tid + (t & 1) * 256;   // 0..511
            int row = cid >> 2;
            int c16 = cid & 3;
            const void* src = srcs[t2] + (size_t)row * GK + k0 + c16 * 8;
            uint32_t dst = sb + (uint32_t)(stage * STG_B + t2 * TEN_B + row * BSTRB + c16 * 16);
            cp16(dst, src);
        }
        CP_COMMIT();
    };

    issue(0, 0);

    for (int c = 0; c < GK / 32; c++) {
        const int cur = c & 1;
        CP_WAIT0();
        __syncthreads();
        if (c + 1 < GK / 32) issue(cur ^ 1, (c + 1) * 32);

        const uint32_t sOff = (uint32_t)(cur * STG_B);
        #pragma unroll
        for (int kt = 0; kt < 2; kt++) {
            const uint32_t ktB = (uint32_t)(kt * 32);
            unsigned af[4][4], wf[2][4];
            #pragma unroll
            for (int mt = 0; mt < 4; mt++)
                ldsm_x4(af[mt], aB + sOff + (uint32_t)(mt * 16 * BSTRB) + ktB);
            #pragma unroll
            for (int p = 0; p < 2; p++)
                ldsm_x4(wf[p], wB + sOff + (uint32_t)(p * 16 * BSTRB) + ktB);
            #pragma unroll
            for (int mt = 0; mt < 4; mt++) {
                #pragma unroll
                for (int p = 0; p < 2; p++) {
                    mma_f16(acc[mt][2*p],   af[mt][0], af[mt][1], af[mt][2], af[mt][3],
                            wf[p][0], wf[p][1]);
                    mma_f16(acc[mt][2*p+1], af[mt][0], af[mt][1], af[mt][2], af[mt][3],
                            wf[p][2], wf[p][3]);
                }
            }
        }
        __syncthreads();
    }

    #pragma unroll
    for (int mt = 0; mt < 4; mt++) {
        #pragma unroll
        for (int nt = 0; nt < 4; nt++) {
            int ncol = n0 + wn + nt * 8 + 2 * tig;
            float2 bv = *(const float2*)(bias + ncol);
            int r0 = m0 + wm + mt * 16 + g;
            *(float2*)(C + (size_t)r0 * HIDDEN + ncol) =
                make_float2(scale * (acc[mt][nt][0] + bv.x), scale * (acc[mt][nt][1] + bv.y));
            *(float2*)(C + (size_t)(r0 + 8) * HIDDEN + ncol) =
                make_float2(scale * (acc[mt][nt][2] + bv.x), scale * (acc[mt][nt][3] + bv.y));
        }
    }
}

// ---------------------------------------------------------------------------
// Flash attention (unchanged from R6 best): tf32 mma + ldmatrix, single-
// buffered K/V, 2 CTAs/SM, register prefetch, two syncs per 64-key chunk.
// ---------------------------------------------------------------------------
#define QSS 68
#define VSS 72
#define ATTN_SMEM ((128*QSS + 128*QSS + 64*QSS + 64*VSS) * 4)   // 105472 B

__global__ __launch_bounds__(256, 2) void attn_tf32(
    const float* __restrict__ Q, const float* __restrict__ K,
    const float* __restrict__ V, const float* __restrict__ bias,
    const int* __restrict__ flags, float* __restrict__ O)
{
    extern __shared__ unsigned sm[];
    unsigned* Qs = sm;
    unsigned* Ps = Qs + 128 * QSS;
    unsigned* Ks = Ps + 128 * QSS;
    unsigned* Vs = Ks + 64 * QSS;
    const uint32_t sbQ = smem_u32(Qs);
    const uint32_t sbP = smem_u32(Ps);
    const uint32_t sbK = smem_u32(Ks);

    const int tid  = threadIdx.x;
    const int lane = tid & 31;
    const int warp = tid >> 5;
    const int g    = lane >> 2;
    const int tig  = lane & 3;
    const int q0   = blockIdx.x * 128;
    const int h    = blockIdx.y;
    const int b    = blockIdx.z;
    const size_t base = (size_t)b * SEQ * HIDDEN + (size_t)h * HD;
    const int qb   = warp * 16;

    const int srow = tid >> 4;
    const int sdq  = (tid & 15) << 2;

    const int rA = (lane & 7) + ((lane >> 3) & 1) * 8;
    const int cA = (lane >> 4) * 4;
    const uint32_t qAddr0 = sbQ + (uint32_t)(((qb + rA) * QSS + cA) * 4);
    const uint32_t pAddr0 = sbP + (uint32_t)(((qb + rA) * QSS + cA) * 4);
    const int rB = (lane & 7) + (lane >> 4) * 8;
    const int cB = ((lane >> 3) & 1) * 4;
    const uint32_t kAddr0 = sbK + (uint32_t)((rB * QSS + cB) * 4);

    #pragma unroll
    for (int r = 0; r < 8; r++) {
        int row = srow + 16 * r;
        float4 v = *(const float4*)(Q + base + (size_t)(q0 + row) * HIDDEN + sdq);
        *(uint4*)&Qs[row * QSS + sdq] =
            make_uint4(f2tf(v.x), f2tf(v.y), f2tf(v.z), f2tf(v.w));
    }

    float4 pk[4], pv4[4];
    #pragma unroll
    for (int r = 0; r < 4; r++) {
        int row = srow + 16 * r;
        pk[r]  = *(const float4*)(K + base + (size_t)row * HIDDEN + sdq);
        pv4[r] = *(const float4*)(V + base + (size_t)row * HIDDEN + sdq);
    }
    #pragma unroll
    for (int r = 0; r < 4; r++) {
        int row = srow + 16 * r;
        *(uint4*)&Ks[row * QSS + sdq] =
            make_uint4(f2tf(pk[r].x), f2tf(pk[r].y), f2tf(pk[r].z), f2tf(pk[r].w));
        *(uint4*)&Vs[row * VSS + sdq] =
            make_uint4(f2tf(pv4[r].x), f2tf(pv4[r].y), f2tf(pv4[r].z), f2tf(pv4[r].w));
    }
    __syncthreads();

    float o[8][4];
    float mr[2], lr[2];
    mr[0] = mr[1] = -1e30f;
    lr[0] = lr[1] = 0.f;
    #pragma unroll
    for (int nt = 0; nt < 8; nt++)
        #pragma unroll
        for (int e = 0; e < 4; e++) o[nt][e] = 0.f;

    const int qr = qb + g;

    for (int c = 0; c < SEQ / 64; c++) {
        const bool more = (c + 1 < SEQ / 64);

        if (more) {
            const int k1 = (c + 1) * 64;
            #pragma unroll
            for (int r = 0; r < 4; r++) {
                int row = srow + 16 * r;
                pk[r]  = *(const float4*)(K + base + (size_t)(k1 + row) * HIDDEN + sdq);
                pv4[r] = *(const float4*)(V + base + (size_t)(k1 + row) * HIDDEN + sdq);
            }
        }

        float s[8][4];
        #pragma unroll
        for (int nt = 0; nt < 8; nt++)
            #pragma unroll
            for (int e = 0; e < 4; e++) s[nt][e] = 0.f;

        #pragma unroll
        for (int kt = 0; kt < 8; kt++) {
            const uint32_t kbB = (uint32_t)(kt * 8 * 4);
            unsigned qf[4], kf[4][4];
            ldsm_x4(qf, qAddr0 + kbB);
            #pragma unroll
            for (int p = 0; p < 4; p++)
                ldsm_x4(kf[p], kAddr0 + (uint32_t)(p * 16 * QSS * 4) + kbB);
            #pragma unroll
            for (int p = 0; p < 4; p++) {
                mma_tf32(s[2*p],   qf[0], qf[1], qf[2], qf[3], kf[p][0], kf[p][1]);
                mma_tf32(s[2*p+1], qf[0], qf[1], qf[2], qf[3], kf[p][2], kf[p][3]);
            }
        }

        if (flags[blockIdx.x * (SEQ / 64) + c]) {
            const int k0 = c * 64;
            int r0 = q0 + qr;
            #pragma unroll
            for (int nt = 0; nt < 8; nt++) {
                int col = k0 + nt * 8 + 2 * tig;
                float2 b0 = *(const float2*)(bias + (size_t)r0 * SEQ + col);
                s[nt][0] += b0.x; s[nt][1] += b0.y;
                float2 b1 = *(const float2*)(bias + (size_t)(r0 + 8) * SEQ + col);
                s[nt][2] += b1.x; s[nt][3] += b1.y;
            }
        }

        #pragma unroll
        for (int h2 = 0; h2 < 2; h2++) {
            float mx = -1e30f;
            #pragma unroll
            for (int nt = 0; nt < 8; nt++)
                mx = fmaxf(mx, fmaxf(s[nt][2 * h2], s[nt][2 * h2 + 1]));
            mx = fmaxf(mx, __shfl_xor_sync(0xffffffffu, mx, 1));
            mx = fmaxf(mx, __shfl_xor_sync(0xffffffffu, mx, 2));
            float mn = fmaxf(mr[h2], mx);
            float al = __expf(mr[h2] - mn);
            mr[h2] = mn;
            float sum = 0.f;
            #pragma unroll
            for (int nt = 0; nt < 8; nt++) {
                float p0 = __expf(s[nt][2 * h2]     - mn);
                float p1 = __expf(s[nt][2 * h2 + 1] - mn);
                s[nt][2 * h2] = p0;  s[nt][2 * h2 + 1] = p1;
                sum += p0 + p1;
            }
            sum += __shfl_xor_sync(0xffffffffu, sum, 1);
            sum += __shfl_xor_sync(0xffffffffu, sum, 2);
            lr[h2] = lr[h2] * al + sum;
            #pragma unroll
            for (int nt = 0; nt < 8; nt++) {
                o[nt][2 * h2]     *= al;
                o[nt][2 * h2 + 1] *= al;
            }
        }

        #pragma unroll
        for (int nt = 0; nt < 8; nt++) {
            int col = nt * 8 + 2 * tig;
            *(uint2*)&Ps[qr * QSS + col] =
                make_uint2(f2tf(s[nt][0]), f2tf(s[nt][1]));
            *(uint2*)&Ps[(qr + 8) * QSS + col] =
                make_uint2(f2tf(s[nt][2]), f2tf(s[nt][3]));
        }
        __syncwarp();

        #pragma unroll
        for (int kt = 0; kt < 8; kt++) {
            const int kb = kt * 8;
            unsigned pf[4];
            ldsm_x4(pf, pAddr0 + (uint32_t)(kb * 4));
            #pragma unroll
            for (int nt = 0; nt < 8; nt++) {
                const unsigned* vp = Vs + (kb + tig) * VSS + nt * 8 + g;
                mma_tf32(o[nt], pf[0], pf[1], pf[2], pf[3], vp[0], vp[4 * VSS]);
            }
        }

        if (more) {
            __syncthreads();
            #pragma unroll
            for (int r = 0; r < 4; r++) {
                int row = srow + 16 * r;
                *(uint4*)&Ks[row * QSS + sdq] =
                    make_uint4(f2tf(pk[r].x), f2tf(pk[r].y), f2tf(pk[r].z), f2tf(pk[r].w));
                *(uint4*)&Vs[row * VSS + sdq] =
                    make_uint4(f2tf(pv4[r].x), f2tf(pv4[r].y), f2tf(pv4[r].z), f2tf(pv4[r].w));
            }
            __syncthreads();
        }
    }

    float inv0 = 1.f / lr[0];
    float inv1 = 1.f / lr[1];
    int r0 = q0 + qr;
    #pragma unroll
    for (int nt = 0; nt < 8; nt++) {
        int col = h * HD + nt * 8 + 2 * tig;
        *(float2*)(O + (size_t)b * SEQ * HIDDEN + (size_t)r0 * HIDDEN + col) =
            make_float2(o[nt][0] * inv0, o[nt][1] * inv0);
        *(float2*)(O + (size_t)b * SEQ * HIDDEN + (size_t)(r0 + 8) * HIDDEN + col) =
            make_float2(o[nt][2] * inv1, o[nt][3] * inv1);
    }
}

// ---------------------------------------------------------------------------
extern "C" void kernel_launch(void* const* d_in, const int* in_sizes, int n_in,
                              void* d_out, int out_size)
{
    (void)in_sizes; (void)n_in; (void)out_size;
    const float* query = (const float*)d_in[0];
    const float* bias  = (const float*)d_in[1];
    const float* wq    = (const float*)d_in[2];
    const float* bq    = (const float*)d_in[3];
    const float* wk    = (const float*)d_in[4];
    const float* bk    = (const float*)d_in[5];
    const float* wv    = (const float*)d_in[6];
    const float* bv    = (const float*)d_in[7];
    const float* wo    = (const float*)d_in[8];
    const float* bo    = (const float*)d_in[9];
    float* out = (float*)d_out;

    float *qb, *kb, *vb, *ab;
    int* bfl;
    __half *qh, *ah, *wh;
    cudaGetSymbolAddress((void**)&qb, g_q);
    cudaGetSymbolAddress((void**)&kb, g_k);
    cudaGetSymbolAddress((void**)&vb, g_v);
    cudaGetSymbolAddress((void**)&ab, g_attn);
    cudaGetSymbolAddress((void**)&bfl, g_bflag);
    cudaGetSymbolAddress((void**)&qh, g_qh);
    cudaGetSymbolAddress((void**)&ah, g_ah);
    cudaGetSymbolAddress((void**)&wh, g_wh);

    const size_t WN = (size_t)HIDDEN * HIDDEN;   // 1048576

    cudaFuncSetAttribute(gemm_f16,
                         cudaFuncAttributeMaxDynamicSharedMemorySize, GEMM_SMEM);
    cudaFuncSetAttribute(attn_tf32,
                         cudaFuncAttributeMaxDynamicSharedMemorySize, ATTN_SMEM);

    bias_flags<<<(SEQ/128) * (SEQ/64), 256>>>(bias, bfl);

    const int actN4 = (int)((size_t)M_TOT * HIDDEN / 4);   // 2M
    const int wN4   = (int)(WN / 4);                       // 256K
    conv_h<<<(actN4 + 255) / 256, 256>>>(query, qh, actN4);
    conv_h<<<(wN4 + 255) / 256, 256>>>(wq, wh + 0 * WN, wN4);
    conv_h<<<(wN4 + 255) / 256, 256>>>(wk, wh + 1 * WN, wN4);
    conv_h<<<(wN4 + 255) / 256, 256>>>(wv, wh + 2 * WN, wN4);
    conv_h<<<(wN4 + 255) / 256, 256>>>(wo, wh + 3 * WN, wN4);

    dim3 ggrid(HIDDEN / 128, M_TOT / 128);   // (8, 64)
    const float qscale = 0.125f;             // 64^-0.5

    gemm_f16<<<ggrid, 256, GEMM_SMEM>>>(qh, wh + 0*WN, bq, qb, qscale);
    gemm_f16<<<ggrid, 256, GEMM_SMEM>>>(qh, wh + 1*WN, bk, kb, 1.0f);
    gemm_f16<<<ggrid, 256, GEMM_SMEM>>>(qh, wh + 2*WN, bv, vb, 1.0f);

    dim3 agrid(SEQ / 128, HEADS, BATCH);     // (16, 16, 4)
    attn_tf32<<<agrid, 256, ATTN_SMEM>>>(qb, kb, vb, bias, bfl, ab);

    conv_h<<<(actN4 + 255) / 256, 256>>>(ab, ah, actN4);
    gemm_f16<<<ggrid, 256, GEMM_SMEM>>>(ah, wh + 3*WN, bo, out, 1.0f);
}

// round 14
// speedup vs baseline: 2.1915x; 1.4895x over previous
#include <cuda_runtime.h>
#include <cuda_fp16.h>
#include <cstdint>
#include <math.h>

#define HIDDEN 1024
#define HEADS  16
#define HD     64
#define SEQ    2048
#define BATCH  4
#define M_TOT  (BATCH*SEQ)   // 8192

// ---------------- scratch (device globals: allocation-free) ----------------
__device__ int    g_bflag[(SEQ/128) * (SEQ/64)];
__device__ __half g_xh[(size_t)M_TOT * HIDDEN];     // query (half)
__device__ __half g_wh[4][(size_t)HIDDEN * HIDDEN]; // weights (half)
__device__ __half g_qo[(size_t)M_TOT * HIDDEN];     // Q proj (half, scaled)
__device__ __half g_ko[(size_t)M_TOT * HIDDEN];
__device__ __half g_vo[(size_t)M_TOT * HIDDEN];
__device__ __half g_ao[(size_t)M_TOT * HIDDEN];     // attention out (half)

// ---------------------------------------------------------------------------
// helpers
// ---------------------------------------------------------------------------
__device__ __forceinline__ void mma_f16(float* c,
    unsigned a0, unsigned a1, unsigned a2, unsigned a3,
    unsigned b0, unsigned b1)
{
    asm volatile(
        "mma.sync.aligned.m16n8k16.row.col.f32.f16.f16.f32 "
        "{%0,%1,%2,%3}, {%4,%5,%6,%7}, {%8,%9}, {%0,%1,%2,%3};\n"
        : "+f"(c[0]), "+f"(c[1]), "+f"(c[2]), "+f"(c[3])
        : "r"(a0), "r"(a1), "r"(a2), "r"(a3), "r"(b0), "r"(b1));
}

__device__ __forceinline__ void ldsm_x4(unsigned* r, uint32_t addr) {
    asm volatile(
        "ldmatrix.sync.aligned.m8n8.x4.shared.b16 {%0,%1,%2,%3}, [%4];"
        : "=r"(r[0]), "=r"(r[1]), "=r"(r[2]), "=r"(r[3])
        : "r"(addr));
}

__device__ __forceinline__ void ldsm_x4_t(unsigned* r, uint32_t addr) {
    asm volatile(
        "ldmatrix.sync.aligned.m8n8.x4.trans.shared.b16 {%0,%1,%2,%3}, [%4];"
        : "=r"(r[0]), "=r"(r[1]), "=r"(r[2]), "=r"(r[3])
        : "r"(addr));
}

__device__ __forceinline__ uint32_t smem_u32(const void* p) {
    uint32_t a;
    asm("{ .reg .u64 t; cvta.to.shared.u64 t, %1; cvt.u32.u64 %0, t; }"
        : "=r"(a) : "l"(p));
    return a;
}

__device__ __forceinline__ void cp16(uint32_t dst, const void* src) {
    asm volatile("cp.async.cg.shared.global [%0], [%1], 16;"
                 :: "r"(dst), "l"(src) : "memory");
}
#define CP_COMMIT() asm volatile("cp.async.commit_group;" ::: "memory")
#define CP_WAIT0()  asm volatile("cp.async.wait_group 0;" ::: "memory")

// ---------------------------------------------------------------------------
// f32 -> f16 conversion
// ---------------------------------------------------------------------------
__global__ __launch_bounds__(256) void conv_h(
    const float* __restrict__ in, __half* __restrict__ out, int n4)
{
    int i = blockIdx.x * 256 + threadIdx.x;
    if (i >= n4) return;
    float4 v = ((const float4*)in)[i];
    __half2* op = (__half2*)out;
    op[2*i]   = __floats2half2_rn(v.x, v.y);
    op[2*i+1] = __floats2half2_rn(v.z, v.w);
}

// ---------------------------------------------------------------------------
// bias tile flags
// ---------------------------------------------------------------------------
__global__ __launch_bounds__(256) void bias_flags(const float* __restrict__ bias,
                                                  int* __restrict__ flags)
{
    const int qt = blockIdx.x >> 5;
    const int kt = blockIdx.x & 31;
    const int tid = threadIdx.x;
    bool nz = false;
    #pragma unroll
    for (int r = 0; r < 8; r++) {
        int f   = tid + r * 256;
        int row = f >> 4;
        int cq  = (f & 15) << 2;
        float4 v = *(const float4*)(bias + (size_t)(qt * 128 + row) * SEQ + kt * 64 + cq);
        nz |= (v.x != 0.f) | (v.y != 0.f) | (v.z != 0.f) | (v.w != 0.f);
    }
    int any = __syncthreads_or((int)nz);
    if (tid == 0) flags[blockIdx.x] = any;
}

// ---------------------------------------------------------------------------
// fp16 GEMM (proven R13): C = scale*(A@W^T + bias). CTA 128x128x32, 8 warps,
// warp tile 64x32, m16n8k16. cp.async 2-stage. Output fp32 OR fp16.
// ---------------------------------------------------------------------------
#define GK 1024
#define BSTRB 80
#define TEN_B (128*BSTRB)
#define STG_B (2*TEN_B)
#define GEMM_SMEM (2*STG_B)   // 40960 B

__global__ __launch_bounds__(256, 2) void gemm_f16(
    const __half* __restrict__ Ah, const __half* __restrict__ Wh,
    const float* __restrict__ bias, float* __restrict__ Cf,
    __half* __restrict__ Ch, float scale)
{
    extern __shared__ char gsm[];
    const uint32_t sb = smem_u32(gsm);

    const int tid  = threadIdx.x;
    const int lane = tid & 31;
    const int warp = tid >> 5;
    const int g    = lane >> 2;
    const int tig  = lane & 3;
    const int wm   = (warp >> 2) * 64;
    const int wn   = (warp & 3) * 32;
    const int m0   = blockIdx.y * 128;
    const int n0   = blockIdx.x * 128;

    const __half* srcs[2] = { Ah + (size_t)m0 * GK, Wh + (size_t)n0 * GK };

    const uint32_t aB = sb + (uint32_t)((wm + (lane & 15)) * BSTRB + (lane >> 4) * 16);
    const int wrow = wn + ((lane >> 4) << 3) + (lane & 7);
    const uint32_t wB = sb + TEN_B + (uint32_t)(wrow * BSTRB + ((lane >> 3) & 1) * 16);

    float acc[4][4][4];
    #pragma unroll
    for (int i = 0; i < 4; i++)
        #pragma unroll
        for (int j = 0; j < 4; j++)
            #pragma unroll
            for (int e = 0; e < 4; e++) acc[i][j][e] = 0.f;

    auto issue = [&](int stage, int k0) {
        #pragma unroll
        for (int t = 0; t < 4; t++) {
            int t2  = t >> 1;
            int cid = tid + (t & 1) * 256;
            int row = cid >> 2;
            int c16 = cid & 3;
            const void* src = srcs[t2] + (size_t)row * GK + k0 + c16 * 8;
            uint32_t dst = sb + (uint32_t)(stage * STG_B + t2 * TEN_B + row * BSTRB + c16 * 16);
            cp16(dst, src);
        }
        CP_COMMIT();
    };

    issue(0, 0);

    for (int c = 0; c < GK / 32; c++) {
        const int cur = c & 1;
        CP_WAIT0();
        __syncthreads();
        if (c + 1 < GK / 32) issue(cur ^ 1, (c + 1) * 32);

        const uint32_t sOff = (uint32_t)(cur * STG_B);
        #pragma unroll
        for (int kt = 0; kt < 2; kt++) {
            const uint32_t ktB = (uint32_t)(kt * 32);
            unsigned af[4][4], wf[2][4];
            #pragma unroll
            for (int mt = 0; mt < 4; mt++)
                ldsm_x4(af[mt], aB + sOff + (uint32_t)(mt * 16 * BSTRB) + ktB);
            #pragma unroll
            for (int p = 0; p < 2; p++)
                ldsm_x4(wf[p], wB + sOff + (uint32_t)(p * 16 * BSTRB) + ktB);
            #pragma unroll
            for (int mt = 0; mt < 4; mt++) {
                #pragma unroll
                for (int p = 0; p < 2; p++) {
                    mma_f16(acc[mt][2*p],   af[mt][0], af[mt][1], af[mt][2], af[mt][3],
                            wf[p][0], wf[p][1]);
                    mma_f16(acc[mt][2*p+1], af[mt][0], af[mt][1], af[mt][2], af[mt][3],
                            wf[p][2], wf[p][3]);
                }
            }
        }
        __syncthreads();
    }

    #pragma unroll
    for (int mt = 0; mt < 4; mt++) {
        #pragma unroll
        for (int nt = 0; nt < 4; nt++) {
            int ncol = n0 + wn + nt * 8 + 2 * tig;
            float2 bv = *(const float2*)(bias + ncol);
            int r0 = m0 + wm + mt * 16 + g;
            float v00 = scale * (acc[mt][nt][0] + bv.x);
            float v01 = scale * (acc[mt][nt][1] + bv.y);
            float v10 = scale * (acc[mt][nt][2] + bv.x);
            float v11 = scale * (acc[mt][nt][3] + bv.y);
            if (Ch) {
                *(__half2*)(Ch + (size_t)r0 * HIDDEN + ncol)       = __floats2half2_rn(v00, v01);
                *(__half2*)(Ch + (size_t)(r0 + 8) * HIDDEN + ncol) = __floats2half2_rn(v10, v11);
            } else {
                *(float2*)(Cf + (size_t)r0 * HIDDEN + ncol)       = make_float2(v00, v01);
                *(float2*)(Cf + (size_t)(r0 + 8) * HIDDEN + ncol) = make_float2(v10, v11);
            }
        }
    }
}

// ---------------------------------------------------------------------------
// Flash attention, fp16 m16n8k16. Block = 128 q x (b,h), 8 warps x 16 q rows.
// Q/K/V/attn-out all half. V via ldmatrix.trans. Smem 54KB, 2 CTAs/SM.
// ---------------------------------------------------------------------------
#define HSTRB 144   // bytes per smem row (72 halfs): 16B-aligned, ldsm conflict-free
#define SM_Q 0
#define SM_P (128*HSTRB)            // 18432
#define SM_K (SM_P + 128*HSTRB)     // 36864
#define SM_V (SM_K + 64*HSTRB)      // 46080
#define ATTN_SMEM (SM_V + 64*HSTRB) // 55296

__global__ __launch_bounds__(256, 2) void attn_f16(
    const __half* __restrict__ Q, const __half* __restrict__ K,
    const __half* __restrict__ V, const float* __restrict__ bias,
    const int* __restrict__ flags, __half* __restrict__ O)
{
    extern __shared__ char sm8[];
    const uint32_t sb = smem_u32(sm8);

    const int tid  = threadIdx.x;
    const int lane = tid & 31;
    const int warp = tid >> 5;
    const int g    = lane >> 2;
    const int tig  = lane & 3;
    const int q0   = blockIdx.x * 128;
    const int h    = blockIdx.y;
    const int b    = blockIdx.z;
    const size_t base = (size_t)b * SEQ * HIDDEN + (size_t)h * HD;
    const int qb   = warp * 16;

    const int srow = tid >> 3;      // 0..31
    const int c16  = tid & 7;       // 16B chunk within 128B row

    // fragment addresses
    const uint32_t qA = sb + SM_Q + (uint32_t)((qb + (lane & 15)) * HSTRB + (lane >> 4) * 16);
    const uint32_t pA = sb + SM_P + (uint32_t)((qb + (lane & 15)) * HSTRB + (lane >> 4) * 16);
    const uint32_t kA = sb + SM_K +
        (uint32_t)(((((lane >> 4) & 1) << 3) + (lane & 7)) * HSTRB + ((lane >> 3) & 1) * 16);
    const uint32_t vA = sb + SM_V +
        (uint32_t)(((((lane >> 3) & 1) << 3) + (lane & 7)) * HSTRB + ((lane >> 4) & 1) * 16);

    // stage Q tile (128 rows x 64 halfs)
    #pragma unroll
    for (int r = 0; r < 4; r++) {
        int row = srow + 32 * r;
        *(uint4*)(sm8 + SM_Q + row * HSTRB + c16 * 16) =
            *(const uint4*)(Q + base + (size_t)(q0 + row) * HIDDEN + c16 * 8);
    }

    // stage chunk 0 K/V
    uint4 pk[2], pv[2];
    #pragma unroll
    for (int r = 0; r < 2; r++) {
        int row = srow + 32 * r;
        pk[r] = *(const uint4*)(K + base + (size_t)row * HIDDEN + c16 * 8);
        pv[r] = *(const uint4*)(V + base + (size_t)row * HIDDEN + c16 * 8);
    }
    #pragma unroll
    for (int r = 0; r < 2; r++) {
        int row = srow + 32 * r;
        *(uint4*)(sm8 + SM_K + row * HSTRB + c16 * 16) = pk[r];
        *(uint4*)(sm8 + SM_V + row * HSTRB + c16 * 16) = pv[r];
    }
    __syncthreads();

    float o[8][4];
    float mr[2], lr[2];
    mr[0] = mr[1] = -1e30f;
    lr[0] = lr[1] = 0.f;
    #pragma unroll
    for (int nt = 0; nt < 8; nt++)
        #pragma unroll
        for (int e = 0; e < 4; e++) o[nt][e] = 0.f;

    const int qr = qb + g;

    for (int c = 0; c < SEQ / 64; c++) {
        const bool more = (c + 1 < SEQ / 64);

        if (more) {
            const int k1 = (c + 1) * 64;
            #pragma unroll
            for (int r = 0; r < 2; r++) {
                int row = srow + 32 * r;
                pk[r] = *(const uint4*)(K + base + (size_t)(k1 + row) * HIDDEN + c16 * 8);
                pv[r] = *(const uint4*)(V + base + (size_t)(k1 + row) * HIDDEN + c16 * 8);
            }
        }

        // ---- S = Q @ K^T (16 q x 64 keys x d=64, 4 k-steps) ----
        float s[8][4];
        #pragma unroll
        for (int nt = 0; nt < 8; nt++)
            #pragma unroll
            for (int e = 0; e < 4; e++) s[nt][e] = 0.f;

        #pragma unroll
        for (int kt = 0; kt < 4; kt++) {
            const uint32_t ktB = (uint32_t)(kt * 32);
            unsigned qf[4], kf[4][4];
            ldsm_x4(qf, qA + ktB);
            #pragma unroll
            for (int p = 0; p < 4; p++)
                ldsm_x4(kf[p], kA + (uint32_t)(p * 16 * HSTRB) + ktB);
            #pragma unroll
            for (int p = 0; p < 4; p++) {
                mma_f16(s[2*p],   qf[0], qf[1], qf[2], qf[3], kf[p][0], kf[p][1]);
                mma_f16(s[2*p+1], qf[0], qf[1], qf[2], qf[3], kf[p][2], kf[p][3]);
            }
        }

        // ---- bias (skipped when tile all-zero) ----
        if (flags[blockIdx.x * (SEQ / 64) + c]) {
            const int k0 = c * 64;
            int r0 = q0 + qr;
            #pragma unroll
            for (int nt = 0; nt < 8; nt++) {
                int col = k0 + nt * 8 + 2 * tig;
                float2 b0 = *(const float2*)(bias + (size_t)r0 * SEQ + col);
                s[nt][0] += b0.x; s[nt][1] += b0.y;
                float2 b1 = *(const float2*)(bias + (size_t)(r0 + 8) * SEQ + col);
                s[nt][2] += b1.x; s[nt][3] += b1.y;
            }
        }

        // ---- online softmax ----
        #pragma unroll
        for (int h2 = 0; h2 < 2; h2++) {
            float mx = -1e30f;
            #pragma unroll
            for (int nt = 0; nt < 8; nt++)
                mx = fmaxf(mx, fmaxf(s[nt][2 * h2], s[nt][2 * h2 + 1]));
            mx = fmaxf(mx, __shfl_xor_sync(0xffffffffu, mx, 1));
            mx = fmaxf(mx, __shfl_xor_sync(0xffffffffu, mx, 2));
            float mn = fmaxf(mr[h2], mx);
            float al = __expf(mr[h2] - mn);
            mr[h2] = mn;
            float sum = 0.f;
            #pragma unroll
            for (int nt = 0; nt < 8; nt++) {
                float p0 = __expf(s[nt][2 * h2]     - mn);
                float p1 = __expf(s[nt][2 * h2 + 1] - mn);
                s[nt][2 * h2] = p0;  s[nt][2 * h2 + 1] = p1;
                sum += p0 + p1;
            }
            sum += __shfl_xor_sync(0xffffffffu, sum, 1);
            sum += __shfl_xor_sync(0xffffffffu, sum, 2);
            lr[h2] = lr[h2] * al + sum;
            #pragma unroll
            for (int nt = 0; nt < 8; nt++) {
                o[nt][2 * h2]     *= al;
                o[nt][2 * h2 + 1] *= al;
            }
        }

        // ---- P -> warp-private smem rows (half) ----
        #pragma unroll
        for (int nt = 0; nt < 8; nt++) {
            int colB = (nt * 8 + 2 * tig) * 2;
            *(__half2*)(sm8 + SM_P + qr * HSTRB + colB) =
                __floats2half2_rn(s[nt][0], s[nt][1]);
            *(__half2*)(sm8 + SM_P + (qr + 8) * HSTRB + colB) =
                __floats2half2_rn(s[nt][2], s[nt][3]);
        }
        __syncwarp();

        // ---- O += P @ V (16 q x 64 d x 64 keys, 4 k-steps; V via ldsm.trans) ----
        #pragma unroll
        for (int kt = 0; kt < 4; kt++) {
            unsigned pf[4];
            ldsm_x4(pf, pA + (uint32_t)(kt * 32));
            #pragma unroll
            for (int nb = 0; nb < 4; nb++) {
                unsigned vf[4];
                ldsm_x4_t(vf, vA + (uint32_t)(kt * 16 * HSTRB) + (uint32_t)(nb * 32));
                mma_f16(o[2*nb],   pf[0], pf[1], pf[2], pf[3], vf[0], vf[1]);
                mma_f16(o[2*nb+1], pf[0], pf[1], pf[2], pf[3], vf[2], vf[3]);
            }
        }

        // ---- overwrite K/V with prefetched next chunk ----
        if (more) {
            __syncthreads();
            #pragma unroll
            for (int r = 0; r < 2; r++) {
                int row = srow + 32 * r;
                *(uint4*)(sm8 + SM_K + row * HSTRB + c16 * 16) = pk[r];
                *(uint4*)(sm8 + SM_V + row * HSTRB + c16 * 16) = pv[r];
            }
            __syncthreads();
        }
    }

    // ---- normalize + store (half) to combined layout [B,S,H*D] ----
    float inv0 = 1.f / lr[0];
    float inv1 = 1.f / lr[1];
    int r0 = q0 + qr;
    const size_t bofs = (size_t)b * SEQ * HIDDEN;
    #pragma unroll
    for (int nt = 0; nt < 8; nt++) {
        int col = h * HD + nt * 8 + 2 * tig;
        *(__half2*)(O + bofs + (size_t)r0 * HIDDEN + col) =
            __floats2half2_rn(o[nt][0] * inv0, o[nt][1] * inv0);
        *(__half2*)(O + bofs + (size_t)(r0 + 8) * HIDDEN + col) =
            __floats2half2_rn(o[nt][2] * inv1, o[nt][3] * inv1);
    }
}

// ---------------------------------------------------------------------------
extern "C" void kernel_launch(void* const* d_in, const int* in_sizes, int n_in,
                              void* d_out, int out_size)
{
    (void)in_sizes; (void)n_in; (void)out_size;
    const float* query = (const float*)d_in[0];
    const float* bias  = (const float*)d_in[1];
    const float* wq    = (const float*)d_in[2];
    const float* bq    = (const float*)d_in[3];
    const float* wk    = (const float*)d_in[4];
    const float* bk    = (const float*)d_in[5];
    const float* wv    = (const float*)d_in[6];
    const float* bv    = (const float*)d_in[7];
    const float* wo    = (const float*)d_in[8];
    const float* bo    = (const float*)d_in[9];
    float* out = (float*)d_out;

    int* bfl;
    __half *xh, *wh, *qo, *ko, *vo, *ao;
    cudaGetSymbolAddress((void**)&bfl, g_bflag);
    cudaGetSymbolAddress((void**)&xh, g_xh);
    cudaGetSymbolAddress((void**)&wh, g_wh);
    cudaGetSymbolAddress((void**)&qo, g_qo);
    cudaGetSymbolAddress((void**)&ko, g_ko);
    cudaGetSymbolAddress((void**)&vo, g_vo);
    cudaGetSymbolAddress((void**)&ao, g_ao);

    const size_t WN = (size_t)HIDDEN * HIDDEN;   // 1048576

    cudaFuncSetAttribute(gemm_f16,
                         cudaFuncAttributeMaxDynamicSharedMemorySize, GEMM_SMEM);
    cudaFuncSetAttribute(attn_f16,
                         cudaFuncAttributeMaxDynamicSharedMemorySize, ATTN_SMEM);

    bias_flags<<<(SEQ/128) * (SEQ/64), 256>>>(bias, bfl);

    const int actN4 = (int)((size_t)M_TOT * HIDDEN / 4);
    const int wN4   = (int)(WN / 4);
    conv_h<<<(actN4 + 255) / 256, 256>>>(query, xh, actN4);
    conv_h<<<(wN4 + 255) / 256, 256>>>(wq, wh + 0 * WN, wN4);
    conv_h<<<(wN4 + 255) / 256, 256>>>(wk, wh + 1 * WN, wN4);
    conv_h<<<(wN4 + 255) / 256, 256>>>(wv, wh + 2 * WN, wN4);
    conv_h<<<(wN4 + 255) / 256, 256>>>(wo, wh + 3 * WN, wN4);

    dim3 ggrid(HIDDEN / 128, M_TOT / 128);   // (8, 64)
    const float qscale = 0.125f;             // 64^-0.5

    gemm_f16<<<ggrid, 256, GEMM_SMEM>>>(xh, wh + 0*WN, bq, nullptr, qo, qscale);
    gemm_f16<<<ggrid, 256, GEMM_SMEM>>>(xh, wh + 1*WN, bk, nullptr, ko, 1.0f);
    gemm_f16<<<ggrid, 256, GEMM_SMEM>>>(xh, wh + 2*WN, bv, nullptr, vo, 1.0f);

    dim3 agrid(SEQ / 128, HEADS, BATCH);     // (16, 16, 4)
    attn_f16<<<agrid, 256, ATTN_SMEM>>>(qo, ko, vo, bias, bfl, ao);

    gemm_f16<<<ggrid, 256, GEMM_SMEM>>>(ao, wh + 3*WN, bo, out, nullptr, 1.0f);
}